// round 12
// baseline (speedup 1.0000x reference)
#include <cuda_runtime.h>

#define FULL 0xffffffffu
typedef unsigned long long u64;

__device__ __forceinline__ u64 pk2(float x, float y) {
    u64 r; asm("mov.b64 %0,{%1,%2};" : "=l"(r) : "f"(x), "f"(y)); return r;
}
__device__ __forceinline__ void upk2(u64 v, float& x, float& y) {
    asm("mov.b64 {%0,%1},%2;" : "=f"(x), "=f"(y) : "l"(v));
}
__device__ __forceinline__ u64 swap2(u64 v) {
    float x, y; upk2(v, x, y); return pk2(y, x);
}
__device__ __forceinline__ u64 fma2_(u64 a, u64 b, u64 c) {
    u64 d; asm("fma.rn.f32x2 %0,%1,%2,%3;" : "=l"(d) : "l"(a), "l"(b), "l"(c)); return d;
}
__device__ __forceinline__ u64 mul2_(u64 a, u64 b) {
    u64 d; asm("mul.rn.f32x2 %0,%1,%2;" : "=l"(d) : "l"(a), "l"(b)); return d;
}
__device__ __forceinline__ u64 add2_(u64 a, u64 b) {
    u64 d; asm("add.rn.f32x2 %0,%1,%2;" : "=l"(d) : "l"(a), "l"(b)); return d;
}
__device__ __forceinline__ float2 cmulf(float2 a, float2 b) {
    return make_float2(a.x * b.x - a.y * b.y, a.x * b.y + a.y * b.x);
}

// Layout: each half-warp (16 lanes) holds one batch element.
// State index s (8 bits): bits {7,5,3,1} -> k register index bits {3,2,1,0};
//                         bits {6,4,2,0} -> half-lane (hl) bits {3,2,1,0}.
//
// Partial i-representation: the 4 k-held qubits carry an S gate
// (v[k] = i^{popc(k)} * psi), turning layer-0 local CRX into CRY.

template <int LB, int KB>
__device__ __forceinline__ void gate_local_ry(u64 (&v)[16], float c, float s, int hl) {
    const bool ctrl = ((hl >> LB) & 1) != 0;
    const float cE = ctrl ? c : 1.0f;
    const float sE = ctrl ? s : 0.0f;
    const u64 cc = pk2(cE, cE);
    const u64 sp = pk2(sE, sE);
    const u64 sn = pk2(-sE, -sE);
#pragma unroll
    for (int k = 0; k < 16; ++k) {
        if (k & (1 << KB)) continue;
        const int k1 = k | (1 << KB);
        const u64 t = mul2_(sp, v[k]);                 // s*x0 (before overwrite)
        v[k]  = fma2_(cc, v[k],  mul2_(sn, v[k1]));    // c*x0 - s*x1
        v[k1] = fma2_(cc, v[k1], t);                   // c*x1 + s*x0
    }
}

template <int KB, int LB, bool ISRX>
__device__ __forceinline__ void gate_shfl(u64 (&v)[16], float c, float s, int hl) {
    const u64 cc = pk2(c, c);
    u64 smul;
    if (ISRX) {
        smul = pk2(s, -s);
    } else {
        const float sg = ((hl >> LB) & 1) ? s : -s;
        smul = pk2(sg, sg);
    }
#pragma unroll
    for (int k = 0; k < 16; ++k) {
        if (!(k & (1 << KB))) continue;   // control bit = 0: identity
        float r, i;
        upk2(v[k], r, i);
        const float pr = __shfl_xor_sync(FULL, r, 1 << LB);
        const float pi = __shfl_xor_sync(FULL, i, 1 << LB);
        const u64 p = ISRX ? pk2(pi, pr) : pk2(pr, pi);
        v[k] = fma2_(cc, v[k], mul2_(smul, p));
    }
}

__global__ __launch_bounds__(128)
void quanv_kernel(const float* __restrict__ X, const float* __restrict__ W,
                  float* __restrict__ out, int bs) {
    __shared__ float2 s_cs[16];      // entangler (cos, sin) per gate, block-uniform

    const int tid = threadIdx.x;
    if (tid < 16) {
        const float wangle = W[(tid >> 3) * 16 + (tid & 7)];
        float cw, sw;
        __sincosf(0.5f * wangle, &sw, &cw);
        s_cs[tid] = make_float2(cw, sw);
    }
    __syncthreads();

    const int warp = (blockIdx.x * blockDim.x + tid) >> 5;
    const int lane = tid & 31;
    const int hl = lane & 15;         // half-lane
    const int half = lane & 16;       // half-warp base for shuffles
    const int elem = warp * 2 + (lane >> 4);
    const bool valid = elem < bs;
    const float* __restrict__ x = X + (size_t)(valid ? elem : 0) * 64;

    // ===== Phase 1 (split chain): wire q = lane&7.
    // lo lane (hl<8):  state vector (A,B) after H, gates i=0..4.
    // hi lane (hl>=8): SU(2) first column (a,b) of gates i=5..8 (slot i=4 masked).
    const float Rv = 0.70710678118654752440f;
    const bool lo = (hl < 8);
    const int q = lane & 7;
    u64 A = lo ? pk2(Rv, 0.f) : pk2(1.f, 0.f);
    u64 B = lo ? pk2(Rv, 0.f) : pk2(0.f, 0.f);
    const int ibase = lo ? 0 : 4;
#pragma unroll
    for (int j = 0; j < 5; ++j) {
        const int idx = q * 9 + ibase + j;
        const bool ok = (idx < 64) && (lo || j > 0);
        const float th = ok ? x[idx < 64 ? idx : 0] : 0.f;  // th=0 -> identity gate
        float c, s;
        __sincosf(0.5f * th, &s, &c);
        const u64 cc = pk2(c, c);
        if ((j & 1) == 0) {   // RZ
            A = fma2_(cc, A, mul2_(pk2(s, -s), swap2(A)));
            B = fma2_(cc, B, mul2_(pk2(-s, s), swap2(B)));
        } else {              // RY
            const u64 Aold = A;
            A = fma2_(cc, A, mul2_(pk2(-s, -s), B));
            B = fma2_(cc, B, mul2_(pk2(s, s), Aold));
        }
    }
    // Combine across the lane pair (xor 8): full state = M_hi * (A,B)_lo.
    float2 V;
    {
        const u64 rA = __shfl_xor_sync(FULL, A, 8);
        const u64 rB = __shfl_xor_sync(FULL, B, 8);
        const u64 P1 = lo ? rA : B;
        const u64 P2r = lo ? rB : A;
        float t2x, t2y; upk2(P2r, t2x, t2y);
        const u64 P2 = pk2(lo ? -t2x : t2x, lo ? t2y : -t2y);
        const u64 Q1 = lo ? A : rA;
        const u64 Q2 = lo ? B : rB;
        float p1x, p1y; upk2(P1, p1x, p1y);
        u64 acc = mul2_(pk2(p1x, p1x), Q1);
        acc = fma2_(pk2(-p1y, p1y), swap2(Q1), acc);
        float p2x, p2y; upk2(P2, p2x, p2y);
        acc = fma2_(pk2(p2x, p2x), Q2, acc);
        acc = fma2_(pk2(-p2y, p2y), swap2(Q2), acc);
        upk2(acc, V.x, V.y);   // lo lane: A_f ; hi lane: B_f
    }

    // lp: product over lane-held wires 1,3,5,7 (hl bits 3,2,1,0 select component).
    float2 lp;
    {
        const int b = (hl >> 3) & 1;
        lp.x = __shfl_sync(FULL, V.x, half | (b << 3) | 1);
        lp.y = __shfl_sync(FULL, V.y, half | (b << 3) | 1);
    }
    {
        const int b = (hl >> 2) & 1;
        float2 t;
        t.x = __shfl_sync(FULL, V.x, half | (b << 3) | 3);
        t.y = __shfl_sync(FULL, V.y, half | (b << 3) | 3);
        lp = cmulf(lp, t);
    }
    {
        const int b = (hl >> 1) & 1;
        float2 t;
        t.x = __shfl_sync(FULL, V.x, half | (b << 3) | 5);
        t.y = __shfl_sync(FULL, V.y, half | (b << 3) | 5);
        lp = cmulf(lp, t);
    }
    {
        const int b = hl & 1;
        float2 t;
        t.x = __shfl_sync(FULL, V.x, half | (b << 3) | 7);
        t.y = __shfl_sync(FULL, V.y, half | (b << 3) | 7);
        lp = cmulf(lp, t);
    }

    // k-held wires 0,2,4,6: both components. S (x i) on |1> components
    // enters the partial i-representation.
    float2 w0[2], w2[2], w4[2], w6[2];
#pragma unroll
    for (int b = 0; b < 2; ++b) {
        w0[b].x = __shfl_sync(FULL, V.x, half | (b << 3) | 0);
        w0[b].y = __shfl_sync(FULL, V.y, half | (b << 3) | 0);
        w2[b].x = __shfl_sync(FULL, V.x, half | (b << 3) | 2);
        w2[b].y = __shfl_sync(FULL, V.y, half | (b << 3) | 2);
        w4[b].x = __shfl_sync(FULL, V.x, half | (b << 3) | 4);
        w4[b].y = __shfl_sync(FULL, V.y, half | (b << 3) | 4);
        w6[b].x = __shfl_sync(FULL, V.x, half | (b << 3) | 6);
        w6[b].y = __shfl_sync(FULL, V.y, half | (b << 3) | 6);
    }
    w0[1] = make_float2(-w0[1].y, w0[1].x);   // *= i
    w2[1] = make_float2(-w2[1].y, w2[1].x);
    w4[1] = make_float2(-w4[1].y, w4[1].x);
    w6[1] = make_float2(-w6[1].y, w6[1].x);

    // Build product state: k = (w0bit<<3)|(w2bit<<2)|(w4bit<<1)|w6bit.
    u64 v[16];
    {
        float2 d8[8];
#pragma unroll
        for (int i = 0; i < 2; ++i)
#pragma unroll
            for (int j = 0; j < 2; ++j) {
                const float2 c02 = cmulf(cmulf(w0[i], w2[j]), lp);
#pragma unroll
                for (int n = 0; n < 2; ++n)
                    d8[(((i << 1) | j) << 1) | n] = cmulf(c02, w4[n]);
            }
#pragma unroll
        for (int k = 0; k < 16; ++k) {
            const float2 t = cmulf(d8[k >> 1], w6[k & 1]);
            v[k] = pk2(t.x, t.y);
        }
    }

    // ===== Phase 2: entangling layers. Coefficients via smem broadcast.
    {
#define CGS(L, CI, KB, LB, RX)                                       \
        {                                                            \
            const float2 cs_ = s_cs[(L) * 8 + (CI)];                 \
            gate_shfl<KB, LB, RX>(v, cs_.x, cs_.y, hl);              \
        }
#define CGL(L, CI, LB, KB)                                           \
        {                                                            \
            const float2 cs_ = s_cs[(L) * 8 + (CI)];                 \
            gate_local_ry<LB, KB>(v, cs_.x, cs_.y, hl);              \
        }
        // layer 0 (RX): shuffle gates true RX-form; local gates RY-form (i-rep).
        CGS(0, 0, 3, 3, true)   // (7,6)
        CGL(0, 1, 3, 2)         // (6,5)
        CGS(0, 2, 2, 2, true)   // (5,4)
        CGL(0, 3, 2, 1)         // (4,3)
        CGS(0, 4, 1, 1, true)   // (3,2)
        CGL(0, 5, 1, 0)         // (2,1)
        CGS(0, 6, 0, 0, true)   // (1,0)
        CGL(0, 7, 0, 3)         // (0,7)

        // Leave the i-representation: v[k] *= (-i)^popc(k).
#pragma unroll
        for (int k = 0; k < 16; ++k) {
            const int pc = __popc(k) & 3;
            if (pc == 0) continue;
            float r, i;
            upk2(v[k], r, i);
            if (pc == 1)      v[k] = pk2(i, -r);    // * -i
            else if (pc == 2) v[k] = pk2(-r, -i);   // * -1
            else              v[k] = pk2(-i, r);    // * +i
        }

        // layer 1 (RY): standard representation.
        CGS(1, 0, 3, 3, false)
        CGL(1, 1, 3, 2)
        CGS(1, 2, 2, 2, false)
        CGL(1, 3, 2, 1)
        CGS(1, 4, 1, 1, false)
        CGL(1, 5, 1, 0)
        CGS(1, 6, 0, 0, false)
        CGL(1, 7, 0, 3)
#undef CGS
#undef CGL
    }

    // ===== Measurement (scalar |v|^2: mul + fma per k)
    float p[16];
#pragma unroll
    for (int k = 0; k < 16; ++k) {
        float r, i;
        upk2(v[k], r, i);
        p[k] = fmaf(r, r, i * i);
    }
    float s1[8], ow6 = 0.f;
#pragma unroll
    for (int j = 0; j < 8; ++j) {
        s1[j] = p[2 * j] + p[2 * j + 1];
        ow6 += p[2 * j] - p[2 * j + 1];
    }
    float s2[4], ow4 = 0.f;
#pragma unroll
    for (int j = 0; j < 4; ++j) {
        s2[j] = s1[2 * j] + s1[2 * j + 1];
        ow4 += s1[2 * j] - s1[2 * j + 1];
    }
    const float s30 = s2[0] + s2[1], s31 = s2[2] + s2[3];
    const float ow2 = (s2[0] - s2[1]) + (s2[2] - s2[3]);
    const float ow0 = s30 - s31;
    const float sumP = s30 + s31;

    // Packed butterfly reduce: (ow0,ow2) and (ow4,ow6) within half-warp.
    u64 r02 = pk2(ow0, ow2), r46 = pk2(ow4, ow6);
#pragma unroll
    for (int m = 8; m; m >>= 1) {
        r02 = add2_(r02, __shfl_xor_sync(FULL, r02, m));
        r46 = add2_(r46, __shfl_xor_sync(FULL, r46, m));
    }
    // Walsh on sumP over hl bits.
    float wv = sumP;
#pragma unroll
    for (int st = 0; st < 4; ++st) {
        const int m = 1 << st;
        const float pg = __shfl_xor_sync(FULL, wv, m);
        const float sg = (hl & m) ? -1.f : 1.f;
        wv = fmaf(wv, sg, pg);
    }
    const float ow1 = __shfl_sync(FULL, wv, half | 8);
    const float ow3 = __shfl_sync(FULL, wv, half | 4);
    const float ow5 = __shfl_sync(FULL, wv, half | 2);
    const float ow7 = __shfl_sync(FULL, wv, half | 1);

    if (hl == 0 && valid) {
        float f0, f2, f4, f6;
        upk2(r02, f0, f2);
        upk2(r46, f4, f6);
        float4* po = (float4*)(out + (size_t)elem * 8);
        po[0] = make_float4(f0, ow1, f2, ow3);
        po[1] = make_float4(f4, ow5, f6, ow7);
    }
}

extern "C" void kernel_launch(void* const* d_in, const int* in_sizes, int n_in,
                              void* d_out, int out_size) {
    const float* X = (const float*)d_in[0];
    const float* W = (const float*)d_in[1];
    float* out = (float*)d_out;
    const int bs = in_sizes[0] / 64;
    const int warps = (bs + 1) / 2;      // one element-pair per warp
    const int threads = 128;
    const int wpb = threads / 32;
    const int blocks = (warps + wpb - 1) / wpb;
    quanv_kernel<<<blocks, threads>>>(X, W, out, bs);
}

// round 13
// speedup vs baseline: 1.0269x; 1.0269x over previous
#include <cuda_runtime.h>

#define FULL 0xffffffffu
typedef unsigned long long u64;

__device__ __forceinline__ u64 pk2(float x, float y) {
    u64 r; asm("mov.b64 %0,{%1,%2};" : "=l"(r) : "f"(x), "f"(y)); return r;
}
__device__ __forceinline__ void upk2(u64 v, float& x, float& y) {
    asm("mov.b64 {%0,%1},%2;" : "=f"(x), "=f"(y) : "l"(v));
}
__device__ __forceinline__ u64 swap2(u64 v) {
    float x, y; upk2(v, x, y); return pk2(y, x);
}
__device__ __forceinline__ u64 fma2_(u64 a, u64 b, u64 c) {
    u64 d; asm("fma.rn.f32x2 %0,%1,%2,%3;" : "=l"(d) : "l"(a), "l"(b), "l"(c)); return d;
}
__device__ __forceinline__ u64 mul2_(u64 a, u64 b) {
    u64 d; asm("mul.rn.f32x2 %0,%1,%2;" : "=l"(d) : "l"(a), "l"(b)); return d;
}
__device__ __forceinline__ u64 add2_(u64 a, u64 b) {
    u64 d; asm("add.rn.f32x2 %0,%1,%2;" : "=l"(d) : "l"(a), "l"(b)); return d;
}
__device__ __forceinline__ float2 cmulf(float2 a, float2 b) {
    return make_float2(a.x * b.x - a.y * b.y, a.x * b.y + a.y * b.x);
}

// Layout: each half-warp (16 lanes) holds one batch element.
// State index s (8 bits): bits {7,5,3,1} -> k register index bits {3,2,1,0};
//                         bits {6,4,2,0} -> half-lane (hl) bits {3,2,1,0}.
//
// Partial i-representation: the 4 k-held qubits carry an S gate
// (v[k] = i^{popc(k)} * psi), turning layer-0 local CRX into CRY.

template <int LB, int KB>
__device__ __forceinline__ void gate_local_ry(u64 (&v)[16], float c, float s, int hl) {
    const bool ctrl = ((hl >> LB) & 1) != 0;
    const float cE = ctrl ? c : 1.0f;
    const float sE = ctrl ? s : 0.0f;
    const u64 cc = pk2(cE, cE);
    const u64 sp = pk2(sE, sE);
    const u64 sn = pk2(-sE, -sE);
#pragma unroll
    for (int k = 0; k < 16; ++k) {
        if (k & (1 << KB)) continue;
        const int k1 = k | (1 << KB);
        const u64 t = mul2_(sp, v[k]);                 // s*x0 (before overwrite)
        v[k]  = fma2_(cc, v[k],  mul2_(sn, v[k1]));    // c*x0 - s*x1
        v[k1] = fma2_(cc, v[k1], t);                   // c*x1 + s*x0
    }
}

template <int KB, int LB, bool ISRX>
__device__ __forceinline__ void gate_shfl(u64 (&v)[16], float c, float s, int hl) {
    const u64 cc = pk2(c, c);
    u64 smul;
    if (ISRX) {
        smul = pk2(s, -s);
    } else {
        const float sg = ((hl >> LB) & 1) ? s : -s;
        smul = pk2(sg, sg);
    }
#pragma unroll
    for (int k = 0; k < 16; ++k) {
        if (!(k & (1 << KB))) continue;   // control bit = 0: identity
        float r, i;
        upk2(v[k], r, i);
        const float pr = __shfl_xor_sync(FULL, r, 1 << LB);
        const float pi = __shfl_xor_sync(FULL, i, 1 << LB);
        const u64 p = ISRX ? pk2(pi, pr) : pk2(pr, pi);
        v[k] = fma2_(cc, v[k], mul2_(smul, p));
    }
}

__global__ __launch_bounds__(128, 10)
void quanv_kernel(const float* __restrict__ X, const float* __restrict__ W,
                  float* __restrict__ out, int bs) {
    __shared__ float2 s_cs[16];      // entangler (cos, sin) per gate, block-uniform

    const int tid = threadIdx.x;
    if (tid < 16) {
        const float wangle = W[(tid >> 3) * 16 + (tid & 7)];
        float cw, sw;
        __sincosf(0.5f * wangle, &sw, &cw);
        s_cs[tid] = make_float2(cw, sw);
    }
    __syncthreads();

    const int warp = (blockIdx.x * blockDim.x + tid) >> 5;
    const int lane = tid & 31;
    const int hl = lane & 15;         // half-lane
    const int half = lane & 16;       // half-warp base for shuffles
    const int elem = warp * 2 + (lane >> 4);
    const bool valid = elem < bs;
    const float* __restrict__ x = X + (size_t)(valid ? elem : 0) * 64;

    // ===== Phase 1 (split chain): wire q = lane&7.
    // lo lane (hl<8):  state vector (A,B) after H, gates i=0..4.
    // hi lane (hl>=8): SU(2) first column (a,b) of gates i=5..8 (slot i=4 masked).
    const float Rv = 0.70710678118654752440f;
    const bool lo = (hl < 8);
    const int q = lane & 7;
    u64 A = lo ? pk2(Rv, 0.f) : pk2(1.f, 0.f);
    u64 B = lo ? pk2(Rv, 0.f) : pk2(0.f, 0.f);
    const int ibase = lo ? 0 : 4;
#pragma unroll
    for (int j = 0; j < 5; ++j) {
        const int idx = q * 9 + ibase + j;
        const bool ok = (idx < 64) && (lo || j > 0);
        const float th = ok ? x[idx < 64 ? idx : 0] : 0.f;  // th=0 -> identity gate
        float c, s;
        __sincosf(0.5f * th, &s, &c);
        const u64 cc = pk2(c, c);
        if ((j & 1) == 0) {   // RZ
            A = fma2_(cc, A, mul2_(pk2(s, -s), swap2(A)));
            B = fma2_(cc, B, mul2_(pk2(-s, s), swap2(B)));
        } else {              // RY
            const u64 Aold = A;
            A = fma2_(cc, A, mul2_(pk2(-s, -s), B));
            B = fma2_(cc, B, mul2_(pk2(s, s), Aold));
        }
    }
    // Combine across the lane pair (xor 8): full state = M_hi * (A,B)_lo.
    float2 V;
    {
        const u64 rA = __shfl_xor_sync(FULL, A, 8);
        const u64 rB = __shfl_xor_sync(FULL, B, 8);
        const u64 P1 = lo ? rA : B;
        const u64 P2r = lo ? rB : A;
        float t2x, t2y; upk2(P2r, t2x, t2y);
        const u64 P2 = pk2(lo ? -t2x : t2x, lo ? t2y : -t2y);
        const u64 Q1 = lo ? A : rA;
        const u64 Q2 = lo ? B : rB;
        float p1x, p1y; upk2(P1, p1x, p1y);
        u64 acc = mul2_(pk2(p1x, p1x), Q1);
        acc = fma2_(pk2(-p1y, p1y), swap2(Q1), acc);
        float p2x, p2y; upk2(P2, p2x, p2y);
        acc = fma2_(pk2(p2x, p2x), Q2, acc);
        acc = fma2_(pk2(-p2y, p2y), swap2(Q2), acc);
        upk2(acc, V.x, V.y);   // lo lane: A_f ; hi lane: B_f
    }

    // lp: product over lane-held wires 1,3,5,7 (hl bits 3,2,1,0 select component).
    float2 lp;
    {
        const int b = (hl >> 3) & 1;
        lp.x = __shfl_sync(FULL, V.x, half | (b << 3) | 1);
        lp.y = __shfl_sync(FULL, V.y, half | (b << 3) | 1);
    }
    {
        const int b = (hl >> 2) & 1;
        float2 t;
        t.x = __shfl_sync(FULL, V.x, half | (b << 3) | 3);
        t.y = __shfl_sync(FULL, V.y, half | (b << 3) | 3);
        lp = cmulf(lp, t);
    }
    {
        const int b = (hl >> 1) & 1;
        float2 t;
        t.x = __shfl_sync(FULL, V.x, half | (b << 3) | 5);
        t.y = __shfl_sync(FULL, V.y, half | (b << 3) | 5);
        lp = cmulf(lp, t);
    }
    {
        const int b = hl & 1;
        float2 t;
        t.x = __shfl_sync(FULL, V.x, half | (b << 3) | 7);
        t.y = __shfl_sync(FULL, V.y, half | (b << 3) | 7);
        lp = cmulf(lp, t);
    }

    // k-held wires 0,2,4,6: both components. S (x i) on |1> components
    // enters the partial i-representation.
    float2 w0[2], w2[2], w4[2], w6[2];
#pragma unroll
    for (int b = 0; b < 2; ++b) {
        w0[b].x = __shfl_sync(FULL, V.x, half | (b << 3) | 0);
        w0[b].y = __shfl_sync(FULL, V.y, half | (b << 3) | 0);
        w2[b].x = __shfl_sync(FULL, V.x, half | (b << 3) | 2);
        w2[b].y = __shfl_sync(FULL, V.y, half | (b << 3) | 2);
        w4[b].x = __shfl_sync(FULL, V.x, half | (b << 3) | 4);
        w4[b].y = __shfl_sync(FULL, V.y, half | (b << 3) | 4);
        w6[b].x = __shfl_sync(FULL, V.x, half | (b << 3) | 6);
        w6[b].y = __shfl_sync(FULL, V.y, half | (b << 3) | 6);
    }
    w0[1] = make_float2(-w0[1].y, w0[1].x);   // *= i
    w2[1] = make_float2(-w2[1].y, w2[1].x);
    w4[1] = make_float2(-w4[1].y, w4[1].x);
    w6[1] = make_float2(-w6[1].y, w6[1].x);

    // Build product state (fused: no d8 array; w's die early).
    // k = (w0bit<<3)|(w2bit<<2)|(w4bit<<1)|w6bit.
    u64 v[16];
#pragma unroll
    for (int i = 0; i < 2; ++i)
#pragma unroll
        for (int j = 0; j < 2; ++j) {
            const float2 c02 = cmulf(cmulf(w0[i], w2[j]), lp);
#pragma unroll
            for (int n = 0; n < 2; ++n) {
                const float2 d = cmulf(c02, w4[n]);
                const int base = ((((i << 1) | j) << 1) | n) << 1;
                const float2 t0 = cmulf(d, w6[0]);
                const float2 t1 = cmulf(d, w6[1]);
                v[base]     = pk2(t0.x, t0.y);
                v[base + 1] = pk2(t1.x, t1.y);
            }
        }

    // ===== Phase 2: entangling layers. Coefficients via smem broadcast.
    {
#define CGS(L, CI, KB, LB, RX)                                       \
        {                                                            \
            const float2 cs_ = s_cs[(L) * 8 + (CI)];                 \
            gate_shfl<KB, LB, RX>(v, cs_.x, cs_.y, hl);              \
        }
#define CGL(L, CI, LB, KB)                                           \
        {                                                            \
            const float2 cs_ = s_cs[(L) * 8 + (CI)];                 \
            gate_local_ry<LB, KB>(v, cs_.x, cs_.y, hl);              \
        }
        // layer 0 (RX): shuffle gates true RX-form; local gates RY-form (i-rep).
        CGS(0, 0, 3, 3, true)   // (7,6)
        CGL(0, 1, 3, 2)         // (6,5)
        CGS(0, 2, 2, 2, true)   // (5,4)
        CGL(0, 3, 2, 1)         // (4,3)
        CGS(0, 4, 1, 1, true)   // (3,2)
        CGL(0, 5, 1, 0)         // (2,1)
        CGS(0, 6, 0, 0, true)   // (1,0)
        CGL(0, 7, 0, 3)         // (0,7)

        // Leave the i-representation: v[k] *= (-i)^popc(k).
#pragma unroll
        for (int k = 0; k < 16; ++k) {
            const int pc = __popc(k) & 3;
            if (pc == 0) continue;
            float r, i;
            upk2(v[k], r, i);
            if (pc == 1)      v[k] = pk2(i, -r);    // * -i
            else if (pc == 2) v[k] = pk2(-r, -i);   // * -1
            else              v[k] = pk2(-i, r);    // * +i
        }

        // layer 1 (RY): standard representation.
        CGS(1, 0, 3, 3, false)
        CGL(1, 1, 3, 2)
        CGS(1, 2, 2, 2, false)
        CGL(1, 3, 2, 1)
        CGS(1, 4, 1, 1, false)
        CGL(1, 5, 1, 0)
        CGS(1, 6, 0, 0, false)
        CGL(1, 7, 0, 3)
#undef CGS
#undef CGL
    }

    // ===== Measurement (scalar |v|^2: mul + fma per k)
    float p[16];
#pragma unroll
    for (int k = 0; k < 16; ++k) {
        float r, i;
        upk2(v[k], r, i);
        p[k] = fmaf(r, r, i * i);
    }
    float s1[8], ow6 = 0.f;
#pragma unroll
    for (int j = 0; j < 8; ++j) {
        s1[j] = p[2 * j] + p[2 * j + 1];
        ow6 += p[2 * j] - p[2 * j + 1];
    }
    float s2[4], ow4 = 0.f;
#pragma unroll
    for (int j = 0; j < 4; ++j) {
        s2[j] = s1[2 * j] + s1[2 * j + 1];
        ow4 += s1[2 * j] - s1[2 * j + 1];
    }
    const float s30 = s2[0] + s2[1], s31 = s2[2] + s2[3];
    const float ow2 = (s2[0] - s2[1]) + (s2[2] - s2[3]);
    const float ow0 = s30 - s31;
    const float sumP = s30 + s31;

    // Packed butterfly reduce: (ow0,ow2) and (ow4,ow6) within half-warp.
    u64 r02 = pk2(ow0, ow2), r46 = pk2(ow4, ow6);
#pragma unroll
    for (int m = 8; m; m >>= 1) {
        r02 = add2_(r02, __shfl_xor_sync(FULL, r02, m));
        r46 = add2_(r46, __shfl_xor_sync(FULL, r46, m));
    }
    // Walsh on sumP over hl bits.
    float wv = sumP;
#pragma unroll
    for (int st = 0; st < 4; ++st) {
        const int m = 1 << st;
        const float pg = __shfl_xor_sync(FULL, wv, m);
        const float sg = (hl & m) ? -1.f : 1.f;
        wv = fmaf(wv, sg, pg);
    }
    const float ow1 = __shfl_sync(FULL, wv, half | 8);
    const float ow3 = __shfl_sync(FULL, wv, half | 4);
    const float ow5 = __shfl_sync(FULL, wv, half | 2);
    const float ow7 = __shfl_sync(FULL, wv, half | 1);

    if (hl == 0 && valid) {
        float f0, f2, f4, f6;
        upk2(r02, f0, f2);
        upk2(r46, f4, f6);
        float4* po = (float4*)(out + (size_t)elem * 8);
        po[0] = make_float4(f0, ow1, f2, ow3);
        po[1] = make_float4(f4, ow5, f6, ow7);
    }
}

extern "C" void kernel_launch(void* const* d_in, const int* in_sizes, int n_in,
                              void* d_out, int out_size) {
    const float* X = (const float*)d_in[0];
    const float* W = (const float*)d_in[1];
    float* out = (float*)d_out;
    const int bs = in_sizes[0] / 64;
    const int warps = (bs + 1) / 2;      // one element-pair per warp
    const int threads = 128;
    const int wpb = threads / 32;
    const int blocks = (warps + wpb - 1) / wpb;
    quanv_kernel<<<blocks, threads>>>(X, W, out, bs);
}